// round 11
// baseline (speedup 1.0000x reference)
#include <cuda_runtime.h>
#include <cuda_bf16.h>
#include <cstdint>

#define EPSQ 1e-7f
typedef __nv_bfloat16 bf16;

// ---------------- static device scratch ----------------
__device__ bf16  g_Uh[(size_t)64*1024*512];   // U hi, k-major (64 MiB)
__device__ bf16  g_Ul[(size_t)64*1024*512];   // U lo
__device__ bf16  g_th[(size_t)64*32*512];     // t hi [b][n][d]
__device__ bf16  g_tl[(size_t)64*32*512];
__device__ bf16  g_ch[(size_t)64*32*1024];    // c hi [b][n][i]
__device__ bf16  g_cl[(size_t)64*32*1024];
__device__ float g_L [(size_t)64*1024*32];    // logits [b][i][n]
__device__ float g_V [(size_t)64*32*512];     // V [b][n][d]
__device__ float g_V0[64*512];
__device__ float g_Wt[(size_t)2048*512];      // W^T [z][d]
__device__ float g_Vpart[(size_t)64*64*512];  // per-chunk partial sums of U

// ---------------- helpers ----------------
__device__ __forceinline__ uint32_t smem_u32(const void* p) {
    uint32_t a;
    asm("{ .reg .u64 t; cvta.to.shared.u64 t, %1; cvt.u32.u64 %0, t; }" : "=r"(a) : "l"(p));
    return a;
}
__device__ __forceinline__ void cpa16(uint32_t dst, const void* src) {
    asm volatile("cp.async.cg.shared.global [%0], [%1], 16;" :: "r"(dst), "l"(src));
}
__device__ __forceinline__ void cpa_commit() {
    asm volatile("cp.async.commit_group;" ::: "memory");
}
template<int N> __device__ __forceinline__ void cpa_wait() {
    asm volatile("cp.async.wait_group %0;" :: "n"(N) : "memory");
}
__device__ __forceinline__ void ldsm4(uint32_t* r, uint32_t a) {
    asm volatile("ldmatrix.sync.aligned.m8n8.x4.shared.b16 {%0,%1,%2,%3}, [%4];"
                 : "=r"(r[0]), "=r"(r[1]), "=r"(r[2]), "=r"(r[3]) : "r"(a));
}
__device__ __forceinline__ void ldsm4t(uint32_t* r, uint32_t a) {
    asm volatile("ldmatrix.sync.aligned.m8n8.x4.trans.shared.b16 {%0,%1,%2,%3}, [%4];"
                 : "=r"(r[0]), "=r"(r[1]), "=r"(r[2]), "=r"(r[3]) : "r"(a));
}
__device__ __forceinline__ void mma16816(float* c, const uint32_t* a, const uint32_t* b) {
    asm volatile(
        "mma.sync.aligned.m16n8k16.row.col.f32.bf16.bf16.f32 "
        "{%0,%1,%2,%3}, {%4,%5,%6,%7}, {%8,%9}, {%0,%1,%2,%3};"
        : "+f"(c[0]), "+f"(c[1]), "+f"(c[2]), "+f"(c[3])
        : "r"(a[0]), "r"(a[1]), "r"(a[2]), "r"(a[3]), "r"(b[0]), "r"(b[1]));
}
__device__ __forceinline__ bf16 bhi(float v) { return __float2bfloat16(v); }
__device__ __forceinline__ bf16 blo(float v, bf16 h) {
    return __float2bfloat16(v - __bfloat162float(h));
}

// ------- prep: U -> (Uh, Ul) split bf16 + per-chunk partial sums -------
// grid (64 i-chunks of 16, 64 b), 256 threads
__global__ void __launch_bounds__(256) k_prep_u(const float* __restrict__ U) {
    int ci = blockIdx.x, b = blockIdx.y;
    int t = threadIdx.x, dq = t & 127, ig = t >> 7;
    size_t base = (((size_t)b * 1024) + ci * 16 + ig * 8) * 512 + dq * 4;
    float4 s = make_float4(0.f, 0.f, 0.f, 0.f);
    #pragma unroll
    for (int r = 0; r < 8; r++) {
        size_t idx = base + (size_t)r * 512;
        float4 v = *(const float4*)(U + idx);
        bf16 h0 = bhi(v.x), h1 = bhi(v.y), h2 = bhi(v.z), h3 = bhi(v.w);
        __nv_bfloat162* dh = (__nv_bfloat162*)(g_Uh + idx);
        __nv_bfloat162* dl = (__nv_bfloat162*)(g_Ul + idx);
        dh[0] = __nv_bfloat162(h0, h1);  dh[1] = __nv_bfloat162(h2, h3);
        dl[0] = __nv_bfloat162(blo(v.x, h0), blo(v.y, h1));
        dl[1] = __nv_bfloat162(blo(v.z, h2), blo(v.w, h3));
        s.x += v.x; s.y += v.y; s.z += v.z; s.w += v.w;
    }
    __shared__ float4 part[2][128];
    part[ig][dq] = s;
    __syncthreads();
    if (ig == 0) {
        float4 a = part[0][dq], c = part[1][dq];
        a.x += c.x; a.y += c.y; a.z += c.z; a.w += c.w;
        *(float4*)(g_Vpart + ((size_t)b * 64 + ci) * 512 + dq * 4) = a;
    }
}

// ------- V0[b,d] = (1/32) * sum over 64 chunks of g_Vpart -------
__global__ void __launch_bounds__(256) k_sum_final() {
    int b = blockIdx.x, t = threadIdx.x;
    float a0 = 0.f, a1 = 0.f;
    const float* p = g_Vpart + (size_t)b * 64 * 512;
    #pragma unroll 8
    for (int ci = 0; ci < 64; ci++) {
        a0 += p[(size_t)ci * 512 + t];
        a1 += p[(size_t)ci * 512 + t + 256];
    }
    g_V0[b * 512 + t]       = a0 * (1.0f / 32.0f);
    g_V0[b * 512 + t + 256] = a1 * (1.0f / 32.0f);
}

// ---------------- prep: Wt[z][d] = W[d][z] ----------------
__global__ void k_prep_w(const float* __restrict__ W) {
    int z0 = blockIdx.x * 32, d0 = blockIdx.y * 32;
    __shared__ float ts[32][33];
    int t = threadIdx.x, r = t >> 3, c4 = (t & 7) * 4;
    float4 v = *(const float4*)(W + (size_t)(d0 + r) * 2048 + z0 + c4);
    ts[r][c4 + 0] = v.x; ts[r][c4 + 1] = v.y; ts[r][c4 + 2] = v.z; ts[r][c4 + 3] = v.w;
    __syncthreads();
    float4 o = make_float4(ts[c4 + 0][r], ts[c4 + 1][r], ts[c4 + 2][r], ts[c4 + 3][r]);
    *(float4*)(g_Wt + (size_t)(z0 + r) * 512 + d0 + c4) = o;
}

// ==== fused: out = squash(V.W_n)  [+ t = W_n^T.out -> bf16 hi/lo] ====
// grid (8 b-tiles, 32 n), 256 threads
__global__ void __launch_bounds__(256) k_outt(const float* __restrict__ W,
                                              float* __restrict__ out,
                                              int first, int do_t) {
    int b0 = blockIdx.x * 8, n = blockIdx.y;
    int tid = threadIdx.x;
    __shared__ float V_s[8][512];
    __shared__ float o_s[8][64];
    __shared__ float sq[4][2][2];

    for (int idx = tid; idx < 8 * 512; idx += 256) {
        int bb = idx >> 9, d = idx & 511;
        V_s[bb][d] = first ? g_V0[(b0 + bb) * 512 + d]
                           : g_V[((size_t)(b0 + bb) * 32 + n) * 512 + d];
    }
    __syncthreads();

    // phase 1: out_pre = V . W[:, n*64+dc], 4 independent chains
    int dc = tid & 63, bq = tid >> 6;
    const float* wc = W + n * 64 + dc;
    float p0[4] = {0, 0, 0, 0}, p1[4] = {0, 0, 0, 0};
    #pragma unroll 2
    for (int d = 0; d < 512; d += 4) {
        #pragma unroll
        for (int j = 0; j < 4; j++) {
            float w = __ldg(wc + (size_t)(d + j) * 2048);
            p0[j] = fmaf(V_s[bq][d + j], w, p0[j]);
            p1[j] = fmaf(V_s[bq + 4][d + j], w, p1[j]);
        }
    }
    float a0 = (p0[0] + p0[1]) + (p0[2] + p0[3]);
    float a1 = (p1[0] + p1[1]) + (p1[2] + p1[3]);

    // squash over dc (64 values = 2 warps per b)
    float s0 = a0 * a0, s1 = a1 * a1;
    #pragma unroll
    for (int o = 16; o > 0; o >>= 1) {
        s0 += __shfl_xor_sync(0xffffffffu, s0, o);
        s1 += __shfl_xor_sync(0xffffffffu, s1, o);
    }
    int half = (tid >> 5) & 1;
    if ((tid & 31) == 0) { sq[bq][0][half] = s0; sq[bq][1][half] = s1; }
    __syncthreads();
    float inv0 = rsqrtf(sq[bq][0][0] + sq[bq][0][1] + EPSQ);
    float inv1 = rsqrtf(sq[bq][1][0] + sq[bq][1][1] + EPSQ);
    float o0 = a0 * inv0, o1 = a1 * inv1;
    out[(size_t)(b0 + bq) * 2048 + n * 64 + dc]     = o0;
    out[(size_t)(b0 + bq + 4) * 2048 + n * 64 + dc] = o1;

    if (!do_t) return;

    o_s[bq][dc] = o0;
    o_s[bq + 4][dc] = o1;
    __syncthreads();

    // phase 2: t[bb][d] = sum_dc Wt[n*64+dc][d] * o_s[bb][dc]
    const float* wbase = g_Wt + (size_t)n * 64 * 512;
    float acc[2][8];
    #pragma unroll
    for (int dd = 0; dd < 2; dd++)
        #pragma unroll
        for (int bb = 0; bb < 8; bb++) acc[dd][bb] = 0.f;
    #pragma unroll 4
    for (int c = 0; c < 64; c++) {
        float w0 = wbase[(size_t)c * 512 + tid];
        float w1 = wbase[(size_t)c * 512 + tid + 256];
        #pragma unroll
        for (int bb = 0; bb < 8; bb++) {
            float o = o_s[bb][c];
            acc[0][bb] = fmaf(w0, o, acc[0][bb]);
            acc[1][bb] = fmaf(w1, o, acc[1][bb]);
        }
    }
    #pragma unroll
    for (int bb = 0; bb < 8; bb++)
        #pragma unroll
        for (int dd = 0; dd < 2; dd++) {
            int d = tid + dd * 256;
            size_t o = ((size_t)(b0 + bb) * 32 + n) * 512 + d;
            float v = acc[dd][bb];
            bf16 h = bhi(v);
            g_th[o] = h; g_tl[o] = blo(v, h);
        }
}

// ---- softmax over n per (b,i); emit c hi/lo bf16 [b][n][i] ----
__global__ void __launch_bounds__(128) k_softmax() {
    int ib = blockIdx.x, b = blockIdx.y, t = threadIdx.x;
    const float* lr = g_L + ((size_t)b * 1024 + ib * 128 + t) * 32;
    float v[32];
    #pragma unroll
    for (int g = 0; g < 8; g++) {
        float4 f = *(const float4*)(lr + g * 4);
        v[g * 4] = f.x; v[g * 4 + 1] = f.y; v[g * 4 + 2] = f.z; v[g * 4 + 3] = f.w;
    }
    float mx = v[0];
    #pragma unroll
    for (int n = 1; n < 32; n++) mx = fmaxf(mx, v[n]);
    float sm = 0.f;
    #pragma unroll
    for (int n = 0; n < 32; n++) { v[n] = __expf(v[n] - mx); sm += v[n]; }
    float inv = 1.0f / sm;
    __shared__ __align__(16) bf16 sh[32][128];
    __shared__ __align__(16) bf16 sl[32][128];
    #pragma unroll
    for (int n = 0; n < 32; n++) {
        float c = v[n] * inv;
        bf16 h = bhi(c);
        sh[n][t] = h; sl[n][t] = blo(c, h);
    }
    __syncthreads();
    #pragma unroll
    for (int k = 0; k < 4; k++) {
        int u = t + k * 128;
        int n = u >> 4, g = u & 15;
        size_t o = ((size_t)b * 32 + n) * 1024 + ib * 128 + g * 8;
        *(uint4*)&g_ch[o] = *(const uint4*)&sh[n][g * 8];
        *(uint4*)&g_cl[o] = *(const uint4*)&sl[n][g * 8];
    }
}

// ============ split-bf16 mma.sync GEMM ============
// WHICH=0: L[b][i][n] = U . t^T      M=128/tile (8 tiles), N=32,  K=512
// WHICH=1: V[b][n][d] = c . U        M=32,  N=128/tile (4 tiles), K=1024
#define STAGE      40960
#define BIG_LO     16384
#define SMALLO     32768
#define GEMM_SMEM  (2 * STAGE + 256)

template<int WHICH>
__global__ void __launch_bounds__(256, 1) k_gemm() {
    extern __shared__ char dsm[];
    uint32_t sb0 = (smem_u32(dsm) + 127) & ~127u;
    const int b = blockIdx.y, tile = blockIdx.x;
    const int t = threadIdx.x, w = t >> 5, l = t & 31;
    const int NC = WHICH ? 16 : 8;   // K/64

    float acc[2][2][4];
    #pragma unroll
    for (int mi = 0; mi < 2; mi++)
        #pragma unroll
        for (int ni = 0; ni < 2; ni++)
            #pragma unroll
            for (int q = 0; q < 4; q++) acc[mi][ni][q] = 0.f;

    auto load_chunk = [&](int c, int s) {
        uint32_t stg = sb0 + (uint32_t)s * STAGE;
        if (WHICH == 0) {
            size_t a0 = ((size_t)b * 1024 + tile * 128) * 512 + (size_t)c * 64;
            #pragma unroll
            for (int u = t; u < 1024; u += 256) {
                int row = u >> 3, c16 = u & 7;
                size_t g = a0 + (size_t)row * 512 + c16 * 8;
                uint32_t d = stg + row * 128 + ((c16 * 16) ^ ((row & 7) << 4));
                cpa16(d, g_Uh + g);
                cpa16(d + BIG_LO, g_Ul + g);
            }
            {
                int row = t >> 3, c16 = t & 7;
                size_t g = ((size_t)b * 32 + row) * 512 + (size_t)c * 64 + c16 * 8;
                uint32_t d = stg + SMALLO + row * 128 + ((c16 * 16) ^ ((row & 7) << 4));
                cpa16(d, g_th + g);
                cpa16(d + 4096, g_tl + g);
            }
        } else {
            size_t b0 = ((size_t)b * 1024 + (size_t)c * 64) * 512 + tile * 128;
            #pragma unroll
            for (int u = t; u < 1024; u += 256) {
                int row = u >> 4, c16 = u & 15;
                size_t g = b0 + (size_t)row * 512 + c16 * 8;
                uint32_t d = stg + row * 256 + ((c16 * 16) ^ ((row & 7) << 4));
                cpa16(d, g_Uh + g);
                cpa16(d + BIG_LO, g_Ul + g);
            }
            {
                int row = t >> 3, c16 = t & 7;
                size_t g = ((size_t)b * 32 + row) * 1024 + (size_t)c * 64 + c16 * 8;
                uint32_t d = stg + SMALLO + row * 128 + ((c16 * 16) ^ ((row & 7) << 4));
                cpa16(d, g_ch + g);
                cpa16(d + 4096, g_cl + g);
            }
        }
        cpa_commit();
    };

    auto compute = [&](int s) {
        uint32_t stg = sb0 + (uint32_t)s * STAGE;
        #pragma unroll
        for (int kk = 0; kk < 4; kk++) {
            uint32_t kb = kk * 32;
            uint32_t aH[2][4], aL[2][4], bH[4], bL[4];
            if (WHICH == 0) {
                int mr = (w >> 1) * 32, nb = (w & 1) * 16;
                #pragma unroll
                for (int mi = 0; mi < 2; mi++) {
                    int row = mr + mi * 16 + (l & 7) + (l & 8);
                    uint32_t cb = kb + ((l >> 4) & 1) * 16;
                    uint32_t ad = stg + row * 128 + (cb ^ ((row & 7) << 4));
                    ldsm4(aH[mi], ad);
                    ldsm4(aL[mi], ad + BIG_LO);
                }
                {
                    int row = nb + (l & 7) + ((l >> 4) & 1) * 8;
                    uint32_t cb = kb + ((l >> 3) & 1) * 16;
                    uint32_t ad = stg + SMALLO + row * 128 + (cb ^ ((row & 7) << 4));
                    ldsm4(bH, ad);
                    ldsm4(bL, ad + 4096);
                }
            } else {
                #pragma unroll
                for (int mi = 0; mi < 2; mi++) {
                    int row = mi * 16 + (l & 7) + (l & 8);
                    uint32_t cb = kb + ((l >> 4) & 1) * 16;
                    uint32_t ad = stg + SMALLO + row * 128 + (cb ^ ((row & 7) << 4));
                    ldsm4(aH[mi], ad);
                    ldsm4(aL[mi], ad + 4096);
                }
                {
                    int krow = kk * 16 + (l & 7) + (l & 8);
                    uint32_t cb = w * 32 + ((l >> 4) & 1) * 16;
                    uint32_t ad = stg + krow * 256 + (cb ^ ((krow & 7) << 4));
                    ldsm4t(bH, ad);
                    ldsm4t(bL, ad + BIG_LO);
                }
            }
            #pragma unroll
            for (int mi = 0; mi < 2; mi++)
                #pragma unroll
                for (int ni = 0; ni < 2; ni++) {
                    mma16816(acc[mi][ni], aH[mi], &bH[ni * 2]);
                    mma16816(acc[mi][ni], aH[mi], &bL[ni * 2]);
                    mma16816(acc[mi][ni], aL[mi], &bH[ni * 2]);
                }
        }
    };

    load_chunk(0, 0);
    for (int c = 0; c < NC; c++) {
        if (c + 1 < NC) {
            load_chunk(c + 1, (c + 1) & 1);
            cpa_wait<1>();
        } else {
            cpa_wait<0>();
        }
        __syncthreads();
        compute(c & 1);
        __syncthreads();
    }

    if (WHICH == 0) {
        int mr = (w >> 1) * 32, nb = (w & 1) * 16;
        #pragma unroll
        for (int mi = 0; mi < 2; mi++) {
            int r0 = tile * 128 + mr + mi * 16 + (l >> 2);
            #pragma unroll
            for (int ni = 0; ni < 2; ni++) {
                int col = nb + ni * 8 + 2 * (l & 3);
                *(float2*)(g_L + ((size_t)b * 1024 + r0) * 32 + col) =
                    make_float2(acc[mi][ni][0], acc[mi][ni][1]);
                *(float2*)(g_L + ((size_t)b * 1024 + r0 + 8) * 32 + col) =
                    make_float2(acc[mi][ni][2], acc[mi][ni][3]);
            }
        }
    } else {
        #pragma unroll
        for (int mi = 0; mi < 2; mi++) {
            int n0 = mi * 16 + (l >> 2);
            #pragma unroll
            for (int ni = 0; ni < 2; ni++) {
                int d = tile * 128 + w * 16 + ni * 8 + 2 * (l & 3);
                *(float2*)(g_V + ((size_t)b * 32 + n0) * 512 + d) =
                    make_float2(acc[mi][ni][0], acc[mi][ni][1]);
                *(float2*)(g_V + ((size_t)b * 32 + n0 + 8) * 512 + d) =
                    make_float2(acc[mi][ni][2], acc[mi][ni][3]);
            }
        }
    }
}

// ---------------- launcher ----------------
extern "C" void kernel_launch(void* const* d_in, const int* in_sizes, int n_in,
                              void* d_out, int out_size) {
    const float* U = (const float*)d_in[0];  // [64,1024,512]
    const float* W = (const float*)d_in[1];  // [1,512,2048]
    float* out = (float*)d_out;              // [64,32,64]

    cudaFuncSetAttribute(k_gemm<0>, cudaFuncAttributeMaxDynamicSharedMemorySize, GEMM_SMEM);
    cudaFuncSetAttribute(k_gemm<1>, cudaFuncAttributeMaxDynamicSharedMemorySize, GEMM_SMEM);

    k_prep_u    <<<dim3(64, 64), 256>>>(U);
    k_prep_w    <<<dim3(64, 16), 256>>>(W);
    k_sum_final <<<64, 256>>>();
    k_outt      <<<dim3(8, 32), 256>>>(W, out, 1, 1);   // iter 0 out + t

    for (int it = 0; it < 2; it++) {
        k_gemm<0> <<<dim3(8, 64), 256, GEMM_SMEM>>>();  // logits
        k_softmax <<<dim3(8, 64), 128>>>();
        k_gemm<1> <<<dim3(4, 64), 256, GEMM_SMEM>>>();  // V = c . U
        k_outt    <<<dim3(8, 32), 256>>>(W, out, 0, it == 0);
    }
}

// round 14
// speedup vs baseline: 1.3617x; 1.3617x over previous
#include <cuda_runtime.h>
#include <cuda_bf16.h>
#include <cstdint>

#define EPSQ 1e-7f
typedef __nv_bfloat16 bf16;

// ---------------- static device scratch ----------------
__device__ bf16  g_Uh[(size_t)64*1024*512];   // U hi, k-major (64 MiB)
__device__ bf16  g_Ul[(size_t)64*1024*512];   // U lo
__device__ bf16  g_th[(size_t)64*32*512];     // t hi [b][n][d]
__device__ bf16  g_tl[(size_t)64*32*512];
__device__ bf16  g_ch[(size_t)64*32*1024];    // c hi [b][n][i]
__device__ bf16  g_cl[(size_t)64*32*1024];
__device__ float g_L [(size_t)64*1024*32];    // logits [b][i][n]
__device__ float g_V [(size_t)64*32*512];     // V [b][n][d]
__device__ float g_V0[64*512];
__device__ float g_Wt[(size_t)2048*512];      // W^T [z][d]
__device__ float g_Vpart[(size_t)64*64*512];  // per-chunk partial sums of U

// ---------------- helpers ----------------
__device__ __forceinline__ uint32_t smem_u32(const void* p) {
    uint32_t a;
    asm("{ .reg .u64 t; cvta.to.shared.u64 t, %1; cvt.u32.u64 %0, t; }" : "=r"(a) : "l"(p));
    return a;
}
__device__ __forceinline__ void cpa16(uint32_t dst, const void* src) {
    asm volatile("cp.async.cg.shared.global [%0], [%1], 16;" :: "r"(dst), "l"(src));
}
__device__ __forceinline__ void cpa_commit() {
    asm volatile("cp.async.commit_group;" ::: "memory");
}
template<int N> __device__ __forceinline__ void cpa_wait() {
    asm volatile("cp.async.wait_group %0;" :: "n"(N) : "memory");
}
__device__ __forceinline__ void ldsm4(uint32_t* r, uint32_t a) {
    asm volatile("ldmatrix.sync.aligned.m8n8.x4.shared.b16 {%0,%1,%2,%3}, [%4];"
                 : "=r"(r[0]), "=r"(r[1]), "=r"(r[2]), "=r"(r[3]) : "r"(a));
}
__device__ __forceinline__ void ldsm4t(uint32_t* r, uint32_t a) {
    asm volatile("ldmatrix.sync.aligned.m8n8.x4.trans.shared.b16 {%0,%1,%2,%3}, [%4];"
                 : "=r"(r[0]), "=r"(r[1]), "=r"(r[2]), "=r"(r[3]) : "r"(a));
}
__device__ __forceinline__ void mma16816(float* c, const uint32_t* a, const uint32_t* b) {
    asm volatile(
        "mma.sync.aligned.m16n8k16.row.col.f32.bf16.bf16.f32 "
        "{%0,%1,%2,%3}, {%4,%5,%6,%7}, {%8,%9}, {%0,%1,%2,%3};"
        : "+f"(c[0]), "+f"(c[1]), "+f"(c[2]), "+f"(c[3])
        : "r"(a[0]), "r"(a[1]), "r"(a[2]), "r"(a[3]), "r"(b[0]), "r"(b[1]));
}
__device__ __forceinline__ bf16 bhi(float v) { return __float2bfloat16(v); }
__device__ __forceinline__ bf16 blo(float v, bf16 h) {
    return __float2bfloat16(v - __bfloat162float(h));
}

// ------- prep: U -> (Uh, Ul) split bf16 + per-chunk partial sums -------
__global__ void __launch_bounds__(256) k_prep_u(const float* __restrict__ U) {
    int ci = blockIdx.x, b = blockIdx.y;
    int t = threadIdx.x, dq = t & 127, ig = t >> 7;
    size_t base = (((size_t)b * 1024) + ci * 16 + ig * 8) * 512 + dq * 4;
    float4 s = make_float4(0.f, 0.f, 0.f, 0.f);
    #pragma unroll
    for (int r = 0; r < 8; r++) {
        size_t idx = base + (size_t)r * 512;
        float4 v = *(const float4*)(U + idx);
        bf16 h0 = bhi(v.x), h1 = bhi(v.y), h2 = bhi(v.z), h3 = bhi(v.w);
        __nv_bfloat162* dh = (__nv_bfloat162*)(g_Uh + idx);
        __nv_bfloat162* dl = (__nv_bfloat162*)(g_Ul + idx);
        dh[0] = __nv_bfloat162(h0, h1);  dh[1] = __nv_bfloat162(h2, h3);
        dl[0] = __nv_bfloat162(blo(v.x, h0), blo(v.y, h1));
        dl[1] = __nv_bfloat162(blo(v.z, h2), blo(v.w, h3));
        s.x += v.x; s.y += v.y; s.z += v.z; s.w += v.w;
    }
    __shared__ float4 part[2][128];
    part[ig][dq] = s;
    __syncthreads();
    if (ig == 0) {
        float4 a = part[0][dq], c = part[1][dq];
        a.x += c.x; a.y += c.y; a.z += c.z; a.w += c.w;
        *(float4*)(g_Vpart + ((size_t)b * 64 + ci) * 512 + dq * 4) = a;
    }
}

// ------- V0[b,d] = (1/32) * sum over 64 chunks of g_Vpart -------
__global__ void __launch_bounds__(256) k_sum_final() {
    int b = blockIdx.x, t = threadIdx.x;
    float a0 = 0.f, a1 = 0.f;
    const float* p = g_Vpart + (size_t)b * 64 * 512;
    #pragma unroll 8
    for (int ci = 0; ci < 64; ci++) {
        a0 += p[(size_t)ci * 512 + t];
        a1 += p[(size_t)ci * 512 + t + 256];
    }
    g_V0[b * 512 + t]       = a0 * (1.0f / 32.0f);
    g_V0[b * 512 + t + 256] = a1 * (1.0f / 32.0f);
}

// ---------------- prep: Wt[z][d] = W[d][z] ----------------
__global__ void k_prep_w(const float* __restrict__ W) {
    int z0 = blockIdx.x * 32, d0 = blockIdx.y * 32;
    __shared__ float ts[32][33];
    int t = threadIdx.x, r = t >> 3, c4 = (t & 7) * 4;
    float4 v = *(const float4*)(W + (size_t)(d0 + r) * 2048 + z0 + c4);
    ts[r][c4 + 0] = v.x; ts[r][c4 + 1] = v.y; ts[r][c4 + 2] = v.z; ts[r][c4 + 3] = v.w;
    __syncthreads();
    float4 o = make_float4(ts[c4 + 0][r], ts[c4 + 1][r], ts[c4 + 2][r], ts[c4 + 3][r]);
    *(float4*)(g_Wt + (size_t)(z0 + r) * 512 + d0 + c4) = o;
}

// ==== fused: out = squash(V.W_n)  [+ t = W_n^T.out -> bf16 hi/lo] ====
// grid (16 b-tiles of 4, 32 n), 256 threads, 4 CTAs/SM
__global__ void __launch_bounds__(256, 4) k_outt(const float* __restrict__ W,
                                                 float* __restrict__ out,
                                                 int first, int do_t) {
    int b0 = blockIdx.x * 4, n = blockIdx.y;
    int tid = threadIdx.x;
    __shared__ float V_s[4][512];                  // 8 KB
    __shared__ __align__(16) float W_s[2][64][64]; // 32 KB double-buffered
    __shared__ float o_s[4][64];
    __shared__ float sq[4][2];
    uint32_t sV = smem_u32(V_s), sW = smem_u32(W_s);

    // async-load V rows (4 x 512 floats) as part of group 0
    {
        int bb = tid >> 6, q = tid & 63;    // 2 float4 per thread
        const float* src = first ? (g_V0 + (size_t)(b0 + bb) * 512)
                                 : (g_V + ((size_t)(b0 + bb) * 32 + n) * 512);
        cpa16(sV + (bb * 512 + q * 8) * 4,     src + q * 8);
        cpa16(sV + (bb * 512 + q * 8 + 4) * 4, src + q * 8 + 4);
    }
    // W chunk loader: 64 rows x 64 floats, 4 threads/row x 4 cp.async each
    auto loadW = [&](int c, int s) {
        int r = tid >> 2, q = tid & 3;
        const float* src = W + (size_t)(c * 64 + r) * 2048 + n * 64 + q * 16;
        uint32_t dst = sW + ((s * 64 + r) * 64 + q * 16) * 4;
        #pragma unroll
        for (int j = 0; j < 4; j++) cpa16(dst + j * 16, src + j * 4);
        cpa_commit();
    };
    loadW(0, 0);
    loadW(1, 1);

    int dc = tid & 63, bq = tid >> 6;
    float p0 = 0.f, p1 = 0.f, p2 = 0.f, p3 = 0.f;
    for (int c = 0; c < 8; c++) {
        int s = c & 1;
        cpa_wait<1>();
        __syncthreads();
        #pragma unroll 4
        for (int r = 0; r < 64; r += 4) {
            float w0 = W_s[s][r + 0][dc], w1 = W_s[s][r + 1][dc];
            float w2 = W_s[s][r + 2][dc], w3 = W_s[s][r + 3][dc];
            p0 = fmaf(V_s[bq][c * 64 + r + 0], w0, p0);
            p1 = fmaf(V_s[bq][c * 64 + r + 1], w1, p1);
            p2 = fmaf(V_s[bq][c * 64 + r + 2], w2, p2);
            p3 = fmaf(V_s[bq][c * 64 + r + 3], w3, p3);
        }
        __syncthreads();
        if (c + 2 < 8) loadW(c + 2, s);
        else cpa_commit();   // keep group count consistent
    }
    float a0 = (p0 + p1) + (p2 + p3);

    // squash over dc (64 lanes = 2 warps per b)
    float s0 = a0 * a0;
    #pragma unroll
    for (int o = 16; o > 0; o >>= 1) s0 += __shfl_xor_sync(0xffffffffu, s0, o);
    int half = (tid >> 5) & 1;
    if ((tid & 31) == 0) sq[bq][half] = s0;
    __syncthreads();
    float inv = rsqrtf(sq[bq][0] + sq[bq][1] + EPSQ);
    float o0 = a0 * inv;
    out[(size_t)(b0 + bq) * 2048 + n * 64 + dc] = o0;

    if (!do_t) return;

    o_s[bq][dc] = o0;
    __syncthreads();

    // phase 2: t[bb][d] = sum_dc Wt[n*64+dc][d] * o_s[bb][dc]
    const float* wbase = g_Wt + (size_t)n * 64 * 512;
    float acc[2][4];
    #pragma unroll
    for (int dd = 0; dd < 2; dd++)
        #pragma unroll
        for (int bb = 0; bb < 4; bb++) acc[dd][bb] = 0.f;
    #pragma unroll 4
    for (int c = 0; c < 64; c++) {
        float w0 = __ldg(wbase + (size_t)c * 512 + tid);
        float w1 = __ldg(wbase + (size_t)c * 512 + tid + 256);
        #pragma unroll
        for (int bb = 0; bb < 4; bb++) {
            float o = o_s[bb][c];
            acc[0][bb] = fmaf(w0, o, acc[0][bb]);
            acc[1][bb] = fmaf(w1, o, acc[1][bb]);
        }
    }
    #pragma unroll
    for (int bb = 0; bb < 4; bb++)
        #pragma unroll
        for (int dd = 0; dd < 2; dd++) {
            int d = tid + dd * 256;
            size_t o = ((size_t)(b0 + bb) * 32 + n) * 512 + d;
            float v = acc[dd][bb];
            bf16 h = bhi(v);
            g_th[o] = h; g_tl[o] = blo(v, h);
        }
}

// ---- softmax over n per (b,i); emit c hi/lo bf16 [b][n][i] ----
__global__ void __launch_bounds__(128) k_softmax() {
    int ib = blockIdx.x, b = blockIdx.y, t = threadIdx.x;
    const float* lr = g_L + ((size_t)b * 1024 + ib * 128 + t) * 32;
    float v[32];
    #pragma unroll
    for (int g = 0; g < 8; g++) {
        float4 f = *(const float4*)(lr + g * 4);
        v[g * 4] = f.x; v[g * 4 + 1] = f.y; v[g * 4 + 2] = f.z; v[g * 4 + 3] = f.w;
    }
    float mx = v[0];
    #pragma unroll
    for (int n = 1; n < 32; n++) mx = fmaxf(mx, v[n]);
    float sm = 0.f;
    #pragma unroll
    for (int n = 0; n < 32; n++) { v[n] = __expf(v[n] - mx); sm += v[n]; }
    float inv = 1.0f / sm;
    __shared__ __align__(16) bf16 sh[32][128];
    __shared__ __align__(16) bf16 sl[32][128];
    #pragma unroll
    for (int n = 0; n < 32; n++) {
        float c = v[n] * inv;
        bf16 h = bhi(c);
        sh[n][t] = h; sl[n][t] = blo(c, h);
    }
    __syncthreads();
    #pragma unroll
    for (int k = 0; k < 4; k++) {
        int u = t + k * 128;
        int n = u >> 4, g = u & 15;
        size_t o = ((size_t)b * 32 + n) * 1024 + ib * 128 + g * 8;
        *(uint4*)&g_ch[o] = *(const uint4*)&sh[n][g * 8];
        *(uint4*)&g_cl[o] = *(const uint4*)&sl[n][g * 8];
    }
}

// ============ split-bf16 mma.sync GEMM ============
// WHICH=0: L[b][i][n] = U . t^T      M=128/tile (8 tiles), N=32,  K=512
// WHICH=1: V[b][n][d] = c . U        M=32,  N=128/tile (4 tiles), K=1024
#define STAGE      40960
#define BIG_LO     16384
#define SMALLO     32768
#define GEMM_SMEM  (2 * STAGE + 256)

template<int WHICH>
__global__ void __launch_bounds__(256, 1) k_gemm() {
    extern __shared__ char dsm[];
    uint32_t sb0 = (smem_u32(dsm) + 127) & ~127u;
    const int b = blockIdx.y, tile = blockIdx.x;
    const int t = threadIdx.x, w = t >> 5, l = t & 31;
    const int NC = WHICH ? 16 : 8;   // K/64

    float acc[2][2][4];
    #pragma unroll
    for (int mi = 0; mi < 2; mi++)
        #pragma unroll
        for (int ni = 0; ni < 2; ni++)
            #pragma unroll
            for (int q = 0; q < 4; q++) acc[mi][ni][q] = 0.f;

    auto load_chunk = [&](int c, int s) {
        uint32_t stg = sb0 + (uint32_t)s * STAGE;
        if (WHICH == 0) {
            size_t a0 = ((size_t)b * 1024 + tile * 128) * 512 + (size_t)c * 64;
            #pragma unroll
            for (int u = t; u < 1024; u += 256) {
                int row = u >> 3, c16 = u & 7;
                size_t g = a0 + (size_t)row * 512 + c16 * 8;
                uint32_t d = stg + row * 128 + ((c16 * 16) ^ ((row & 7) << 4));
                cpa16(d, g_Uh + g);
                cpa16(d + BIG_LO, g_Ul + g);
            }
            {
                int row = t >> 3, c16 = t & 7;
                size_t g = ((size_t)b * 32 + row) * 512 + (size_t)c * 64 + c16 * 8;
                uint32_t d = stg + SMALLO + row * 128 + ((c16 * 16) ^ ((row & 7) << 4));
                cpa16(d, g_th + g);
                cpa16(d + 4096, g_tl + g);
            }
        } else {
            size_t b0 = ((size_t)b * 1024 + (size_t)c * 64) * 512 + tile * 128;
            #pragma unroll
            for (int u = t; u < 1024; u += 256) {
                int row = u >> 4, c16 = u & 15;
                size_t g = b0 + (size_t)row * 512 + c16 * 8;
                uint32_t d = stg + row * 256 + ((c16 * 16) ^ ((row & 7) << 4));
                cpa16(d, g_Uh + g);
                cpa16(d + BIG_LO, g_Ul + g);
            }
            {
                int row = t >> 3, c16 = t & 7;
                size_t g = ((size_t)b * 32 + row) * 1024 + (size_t)c * 64 + c16 * 8;
                uint32_t d = stg + SMALLO + row * 128 + ((c16 * 16) ^ ((row & 7) << 4));
                cpa16(d, g_ch + g);
                cpa16(d + 4096, g_cl + g);
            }
        }
        cpa_commit();
    };

    auto compute = [&](int s) {
        uint32_t stg = sb0 + (uint32_t)s * STAGE;
        #pragma unroll
        for (int kk = 0; kk < 4; kk++) {
            uint32_t kb = kk * 32;
            uint32_t aH[2][4], aL[2][4], bH[4], bL[4];
            if (WHICH == 0) {
                int mr = (w >> 1) * 32, nb = (w & 1) * 16;
                #pragma unroll
                for (int mi = 0; mi < 2; mi++) {
                    int row = mr + mi * 16 + (l & 7) + (l & 8);
                    uint32_t cb = kb + ((l >> 4) & 1) * 16;
                    uint32_t ad = stg + row * 128 + (cb ^ ((row & 7) << 4));
                    ldsm4(aH[mi], ad);
                    ldsm4(aL[mi], ad + BIG_LO);
                }
                {
                    int row = nb + (l & 7) + ((l >> 4) & 1) * 8;
                    uint32_t cb = kb + ((l >> 3) & 1) * 16;
                    uint32_t ad = stg + SMALLO + row * 128 + (cb ^ ((row & 7) << 4));
                    ldsm4(bH, ad);
                    ldsm4(bL, ad + 4096);
                }
            } else {
                #pragma unroll
                for (int mi = 0; mi < 2; mi++) {
                    int row = mi * 16 + (l & 7) + (l & 8);
                    uint32_t cb = kb + ((l >> 4) & 1) * 16;
                    uint32_t ad = stg + SMALLO + row * 128 + (cb ^ ((row & 7) << 4));
                    ldsm4(aH[mi], ad);
                    ldsm4(aL[mi], ad + 4096);
                }
                {
                    int krow = kk * 16 + (l & 7) + (l & 8);
                    uint32_t cb = w * 32 + ((l >> 4) & 1) * 16;
                    uint32_t ad = stg + krow * 256 + (cb ^ ((krow & 7) << 4));
                    ldsm4t(bH, ad);
                    ldsm4t(bL, ad + BIG_LO);
                }
            }
            #pragma unroll
            for (int mi = 0; mi < 2; mi++)
                #pragma unroll
                for (int ni = 0; ni < 2; ni++) {
                    mma16816(acc[mi][ni], aH[mi], &bH[ni * 2]);
                    mma16816(acc[mi][ni], aH[mi], &bL[ni * 2]);
                    mma16816(acc[mi][ni], aL[mi], &bH[ni * 2]);
                }
        }
    };

    load_chunk(0, 0);
    for (int c = 0; c < NC; c++) {
        if (c + 1 < NC) {
            load_chunk(c + 1, (c + 1) & 1);
            cpa_wait<1>();
        } else {
            cpa_wait<0>();
        }
        __syncthreads();
        compute(c & 1);
        __syncthreads();
    }

    if (WHICH == 0) {
        int mr = (w >> 1) * 32, nb = (w & 1) * 16;
        #pragma unroll
        for (int mi = 0; mi < 2; mi++) {
            int r0 = tile * 128 + mr + mi * 16 + (l >> 2);
            #pragma unroll
            for (int ni = 0; ni < 2; ni++) {
                int col = nb + ni * 8 + 2 * (l & 3);
                *(float2*)(g_L + ((size_t)b * 1024 + r0) * 32 + col) =
                    make_float2(acc[mi][ni][0], acc[mi][ni][1]);
                *(float2*)(g_L + ((size_t)b * 1024 + r0 + 8) * 32 + col) =
                    make_float2(acc[mi][ni][2], acc[mi][ni][3]);
            }
        }
    } else {
        #pragma unroll
        for (int mi = 0; mi < 2; mi++) {
            int n0 = mi * 16 + (l >> 2);
            #pragma unroll
            for (int ni = 0; ni < 2; ni++) {
                int d = tile * 128 + w * 16 + ni * 8 + 2 * (l & 3);
                *(float2*)(g_V + ((size_t)b * 32 + n0) * 512 + d) =
                    make_float2(acc[mi][ni][0], acc[mi][ni][1]);
                *(float2*)(g_V + ((size_t)b * 32 + n0 + 8) * 512 + d) =
                    make_float2(acc[mi][ni][2], acc[mi][ni][3]);
            }
        }
    }
}

// ---------------- launcher ----------------
extern "C" void kernel_launch(void* const* d_in, const int* in_sizes, int n_in,
                              void* d_out, int out_size) {
    const float* U = (const float*)d_in[0];  // [64,1024,512]
    const float* W = (const float*)d_in[1];  // [1,512,2048]
    float* out = (float*)d_out;              // [64,32,64]

    cudaFuncSetAttribute(k_gemm<0>, cudaFuncAttributeMaxDynamicSharedMemorySize, GEMM_SMEM);
    cudaFuncSetAttribute(k_gemm<1>, cudaFuncAttributeMaxDynamicSharedMemorySize, GEMM_SMEM);

    k_prep_u    <<<dim3(64, 64), 256>>>(U);
    k_prep_w    <<<dim3(64, 16), 256>>>(W);
    k_sum_final <<<64, 256>>>();
    k_outt      <<<dim3(16, 32), 256>>>(W, out, 1, 1);  // iter 0 out + t

    for (int it = 0; it < 2; it++) {
        k_gemm<0> <<<dim3(8, 64), 256, GEMM_SMEM>>>();  // logits
        k_softmax <<<dim3(8, 64), 128>>>();
        k_gemm<1> <<<dim3(4, 64), 256, GEMM_SMEM>>>();  // V = c . U
        k_outt    <<<dim3(16, 32), 256>>>(W, out, 0, it == 0);
    }
}